// round 1
// baseline (speedup 1.0000x reference)
#include <cuda_runtime.h>
#include <math.h>

// Problem dims (fixed by the reference)
#define Bq 32
#define Tq 2048
#define Dq 512
#define Uq 512

// Scratch (no device allocation allowed -> __device__ globals)
__device__ float g_uh[Bq * Uq];        // hidden@Uk + Ub + Wb  (per b,u bias)
__device__ float g_logits[Bq * Tq];    // pre-softmax logits (Vb dropped: softmax-invariant)

// ---------------------------------------------------------------------------
// Kernel 0: g_uh[b,u] = sum_h hidden[b,h]*Uk[h,u] + Ub[u] + Wb[u]
// Tiny (32x512 outputs, K=512). Coalesced over u.
// ---------------------------------------------------------------------------
__global__ void uh_kernel(const float* __restrict__ hidden,
                          const float* __restrict__ Uk,
                          const float* __restrict__ Ub,
                          const float* __restrict__ Wb) {
    int u = blockIdx.x * blockDim.x + threadIdx.x;   // [0,512)
    int b = blockIdx.y;                              // [0,32)
    float acc = Ub[u] + Wb[u];
    const float* h = hidden + b * 512;               // H = 512
    #pragma unroll 8
    for (int k = 0; k < 512; k++)
        acc = fmaf(h[k], Uk[k * Uq + u], acc);
    g_uh[b * Uq + u] = acc;
}

// ---------------------------------------------------------------------------
// Kernel 1 (the hot one): fused  logits[b,t] = sum_u Vk[u]*tanh(features@Wk + bias)
// Tiled GEMM: CTA = 128 rows (one b, tiles align since T%128==0) x full U.
// BM=128, BN=64 (8 U-tiles serial, logit accumulated in regs), BK=32.
// 256 threads, 8x4 micro-tile per thread. wf tile never leaves registers.
// ---------------------------------------------------------------------------
#define BM 128
#define BN 64
#define BK 32
#define ASTR 132   // padded stride for transposed A tile (4-float pad keeps 16B align)

__global__ __launch_bounds__(256, 2)
void logits_kernel(const float* __restrict__ features,
                   const float* __restrict__ Wk,
                   const float* __restrict__ Vk) {
    __shared__ float As[BK * ASTR];   // As[k*ASTR + m]  (transposed for vector reads over m)
    __shared__ float Bs[BK * BN];     // Bs[k*BN + n]
    __shared__ float red[BM];

    const int tid = threadIdx.x;
    const int tx = tid & 15;          // N direction (16)
    const int ty = tid >> 4;          // M direction (16)
    const long row0 = (long)blockIdx.x * BM;     // global (b,t) row
    const int b = (int)(row0 / Tq);

    float rowp[8];
    #pragma unroll
    for (int i = 0; i < 8; i++) rowp[i] = 0.f;

    for (int nt = 0; nt < Uq / BN; nt++) {
        float acc[8][4];
        #pragma unroll
        for (int i = 0; i < 8; i++)
            #pragma unroll
            for (int j = 0; j < 4; j++) acc[i][j] = 0.f;

        for (int kt = 0; kt < Dq / BK; kt++) {
            // --- load A tile: 128x32 floats = 4 float4 per thread, coalesced over k
            #pragma unroll
            for (int it = 0; it < 4; it++) {
                int idx = tid + it * 256;       // 0..1023 float4 slots
                int m   = idx >> 3;             // row in tile
                int k4  = idx & 7;              // float4 index along k
                float4 v = *reinterpret_cast<const float4*>(
                    features + (row0 + m) * Dq + kt * BK + k4 * 4);
                As[(k4 * 4 + 0) * ASTR + m] = v.x;
                As[(k4 * 4 + 1) * ASTR + m] = v.y;
                As[(k4 * 4 + 2) * ASTR + m] = v.z;
                As[(k4 * 4 + 3) * ASTR + m] = v.w;
            }
            // --- load B tile: 32x64 floats = 2 float4 per thread, coalesced over n
            #pragma unroll
            for (int it = 0; it < 2; it++) {
                int idx = tid + it * 256;       // 0..511 float4 slots
                int k   = idx >> 4;
                int n4  = idx & 15;
                float4 v = *reinterpret_cast<const float4*>(
                    Wk + (kt * BK + k) * Uq + nt * BN + n4 * 4);
                *reinterpret_cast<float4*>(&Bs[k * BN + n4 * 4]) = v;
            }
            __syncthreads();

            #pragma unroll
            for (int kk = 0; kk < BK; kk++) {
                float4 a0 = *reinterpret_cast<const float4*>(&As[kk * ASTR + ty * 8]);
                float4 a1 = *reinterpret_cast<const float4*>(&As[kk * ASTR + ty * 8 + 4]);
                float4 bb = *reinterpret_cast<const float4*>(&Bs[kk * BN + tx * 4]);
                float a[8] = {a0.x, a0.y, a0.z, a0.w, a1.x, a1.y, a1.z, a1.w};
                float bv[4] = {bb.x, bb.y, bb.z, bb.w};
                #pragma unroll
                for (int i = 0; i < 8; i++)
                    #pragma unroll
                    for (int j = 0; j < 4; j++)
                        acc[i][j] = fmaf(a[i], bv[j], acc[i][j]);
            }
            __syncthreads();
        }

        // --- epilogue for this U tile: bias + tanh + Vk-weighted fold into row logit
        int n0 = nt * BN + tx * 4;
        float4 vk = *reinterpret_cast<const float4*>(Vk + n0);       // Vk is [U,1]
        float4 uh = *reinterpret_cast<const float4*>(&g_uh[b * Uq + n0]);
        #pragma unroll
        for (int i = 0; i < 8; i++) {
            rowp[i] += vk.x * tanhf(acc[i][0] + uh.x)
                     + vk.y * tanhf(acc[i][1] + uh.y)
                     + vk.z * tanhf(acc[i][2] + uh.z)
                     + vk.w * tanhf(acc[i][3] + uh.w);
        }
    }

    // reduce partial logits across the 16 tx lanes per row
    if (tid < BM) red[tid] = 0.f;
    __syncthreads();
    #pragma unroll
    for (int i = 0; i < 8; i++) atomicAdd(&red[ty * 8 + i], rowp[i]);
    __syncthreads();
    if (tid < BM) g_logits[row0 + tid] = red[tid];
}

// ---------------------------------------------------------------------------
// Kernel 2: softmax over T per batch -> attention weights (written to d_out)
// ---------------------------------------------------------------------------
__global__ void softmax_kernel(float* __restrict__ out_w) {
    const int b = blockIdx.x;
    const int tid = threadIdx.x;   // 256
    __shared__ float sm[256];
    const float* lg = g_logits + b * Tq;

    float mx = -1e30f;
    for (int t = tid; t < Tq; t += 256) mx = fmaxf(mx, lg[t]);
    sm[tid] = mx; __syncthreads();
    for (int s = 128; s > 0; s >>= 1) {
        if (tid < s) sm[tid] = fmaxf(sm[tid], sm[tid + s]);
        __syncthreads();
    }
    mx = sm[0]; __syncthreads();

    float sum = 0.f;
    for (int t = tid; t < Tq; t += 256) sum += expf(lg[t] - mx);
    sm[tid] = sum; __syncthreads();
    for (int s = 128; s > 0; s >>= 1) {
        if (tid < s) sm[tid] += sm[tid + s];
        __syncthreads();
    }
    float inv = 1.f / sm[0];

    for (int t = tid; t < Tq; t += 256)
        out_w[b * Tq + t] = expf(lg[t] - mx) * inv;
}

// ---------------------------------------------------------------------------
// Kernel 3: context[b,d] = sum_t w[b,t] * features[b,t,d]
// grid (D/128, B), 128 threads; weights staged in smem; coalesced over d.
// ---------------------------------------------------------------------------
__global__ void context_kernel(const float* __restrict__ features,
                               const float* __restrict__ w,
                               float* __restrict__ ctx) {
    __shared__ float ws[Tq];
    const int b = blockIdx.y;
    const int d = blockIdx.x * 128 + threadIdx.x;
    for (int t = threadIdx.x; t < Tq; t += 128) ws[t] = w[b * Tq + t];
    __syncthreads();

    const float* f = features + (long)b * Tq * Dq + d;
    float acc = 0.f;
    #pragma unroll 8
    for (int t = 0; t < Tq; t++)
        acc = fmaf(ws[t], f[(long)t * Dq], acc);
    ctx[b * Dq + d] = acc;
}

// ---------------------------------------------------------------------------
extern "C" void kernel_launch(void* const* d_in, const int* in_sizes, int n_in,
                              void* d_out, int out_size) {
    const float* features = (const float*)d_in[0];  // [B,T,D]
    const float* hidden   = (const float*)d_in[1];  // [B,H]
    const float* Wk       = (const float*)d_in[2];  // [D,U]
    const float* Wb       = (const float*)d_in[3];  // [U]
    const float* Uk       = (const float*)d_in[4];  // [H,U]
    const float* Ub       = (const float*)d_in[5];  // [U]
    const float* Vk       = (const float*)d_in[6];  // [U,1]
    // d_in[7] = Vb [1]: uniform logit shift -> softmax-invariant -> unused.

    float* out  = (float*)d_out;
    float* ctx  = out;               // context_vector [B, D]  (tuple output 0)
    float* attw = out + Bq * Dq;     // attention_weights [B, T, 1] (tuple output 1)

    uh_kernel<<<dim3(Uq / 128, Bq), 128>>>(hidden, Uk, Ub, Wb);
    logits_kernel<<<(Bq * Tq) / BM, 256>>>(features, Wk, Vk);
    softmax_kernel<<<Bq, 256>>>(attw);
    context_kernel<<<dim3(Dq / 128, Bq), 128>>>(features, attw, ctx);
}

// round 3
// speedup vs baseline: 1.2807x; 1.2807x over previous
#include <cuda_runtime.h>
#include <math.h>

// Problem dims (fixed by the reference)
#define Bq 32
#define Tq 2048
#define Dq 512
#define Uq 512

// Scratch (no device allocation allowed -> __device__ globals)
__device__ float g_uh[Bq * Uq];        // hidden@Uk + Ub + Wb  (per b,u bias)
__device__ float g_logits[Bq * Tq];    // pre-softmax logits (Vb dropped: softmax-invariant)

// ---- packed fp32x2 helpers (SASS: FFMA2; ptxas never auto-fuses these) ----
// 64-bit asm operands must be integer types for the "l" constraint.
typedef unsigned long long u64;

__device__ __forceinline__ u64 fma2(u64 a, u64 b, u64 c) {
    u64 d;
    asm("fma.rn.f32x2 %0, %1, %2, %3;" : "=l"(d) : "l"(a), "l"(b), "l"(c));
    return d;
}
__device__ __forceinline__ u64 splat2(float x) {
    u64 d;
    asm("mov.b64 %0, {%1, %1};" : "=l"(d) : "f"(x));
    return d;
}
__device__ __forceinline__ void unpack2(u64 d, float& lo, float& hi) {
    asm("mov.b64 {%0, %1}, %2;" : "=f"(lo), "=f"(hi) : "l"(d));
}
__device__ __forceinline__ float tanh_fast(float x) {   // MUFU.TANH, 1 op
    float y;
    asm("tanh.approx.f32 %0, %1;" : "=f"(y) : "f"(x));
    return y;
}

// ---------------------------------------------------------------------------
// Kernel 0: g_uh[b,u] = sum_h hidden[b,h]*Uk[h,u] + Ub[u] + Wb[u]
// ---------------------------------------------------------------------------
__global__ void uh_kernel(const float* __restrict__ hidden,
                          const float* __restrict__ Uk,
                          const float* __restrict__ Ub,
                          const float* __restrict__ Wb) {
    int u = blockIdx.x * blockDim.x + threadIdx.x;   // [0,512)
    int b = blockIdx.y;                              // [0,32)
    float acc = Ub[u] + Wb[u];
    const float* h = hidden + b * 512;               // H = 512
    #pragma unroll 8
    for (int k = 0; k < 512; k++)
        acc = fmaf(h[k], Uk[k * Uq + u], acc);
    g_uh[b * Uq + u] = acc;
}

// ---------------------------------------------------------------------------
// Kernel 1 (hot): logits[b,t] = sum_u Vk[u]*tanh( (features@Wk)[b,t,u] + uh[b,u] )
// BM=128 x BN=64 x BK=32 tile; 256 threads; per-thread 8(M, as 4 f32x2 pairs) x 4(N).
// Inner product uses packed fma.rn.f32x2 -> 2x fma-pipe throughput.
// ---------------------------------------------------------------------------
#define BM 128
#define BN 64
#define BK 32
#define ASTR 132   // padded stride (multiple of 4 -> 16B-aligned vector reads)

__global__ __launch_bounds__(256, 2)
void logits_kernel(const float* __restrict__ features,
                   const float* __restrict__ Wk,
                   const float* __restrict__ Vk) {
    __shared__ float As[BK * ASTR];   // As[k*ASTR + m]  (transposed: pairs along m contiguous)
    __shared__ float Bs[BK * BN];     // Bs[k*BN + n]
    __shared__ float red[BM];

    const int tid = threadIdx.x;
    const int tx = tid & 15;          // N direction (16)
    const int ty = tid >> 4;          // M direction (16)
    const long row0 = (long)blockIdx.x * BM;     // global (b,t) row
    const int b = (int)(row0 / Tq);

    float rowp[8];
    #pragma unroll
    for (int i = 0; i < 8; i++) rowp[i] = 0.f;

    for (int nt = 0; nt < Uq / BN; nt++) {
        u64 acc2[4][4];               // [m-pair][n], each u64 = packed f32x2 (m, m+1)
        #pragma unroll
        for (int p = 0; p < 4; p++)
            #pragma unroll
            for (int j = 0; j < 4; j++) acc2[p][j] = 0ull;

        for (int kt = 0; kt < Dq / BK; kt++) {
            // --- load A tile: 128x32 floats = 4 float4 per thread, coalesced over k
            #pragma unroll
            for (int it = 0; it < 4; it++) {
                int idx = tid + it * 256;       // 0..1023 float4 slots
                int m   = idx >> 3;             // row in tile
                int k4  = idx & 7;              // float4 index along k
                float4 v = *reinterpret_cast<const float4*>(
                    features + (row0 + m) * Dq + kt * BK + k4 * 4);
                As[(k4 * 4 + 0) * ASTR + m] = v.x;
                As[(k4 * 4 + 1) * ASTR + m] = v.y;
                As[(k4 * 4 + 2) * ASTR + m] = v.z;
                As[(k4 * 4 + 3) * ASTR + m] = v.w;
            }
            // --- load B tile: 32x64 floats = 2 float4 per thread, coalesced over n
            #pragma unroll
            for (int it = 0; it < 2; it++) {
                int idx = tid + it * 256;       // 0..511 float4 slots
                int k   = idx >> 4;
                int n4  = idx & 15;
                float4 v = *reinterpret_cast<const float4*>(
                    Wk + (kt * BK + k) * Uq + nt * BN + n4 * 4);
                *reinterpret_cast<float4*>(&Bs[k * BN + n4 * 4]) = v;
            }
            __syncthreads();

            #pragma unroll
            for (int kk = 0; kk < BK; kk++) {
                // a: 8 consecutive floats at ty*8 -> 4 packed pairs (16B-aligned)
                ulonglong2 a01 = *reinterpret_cast<const ulonglong2*>(&As[kk * ASTR + ty * 8]);
                ulonglong2 a23 = *reinterpret_cast<const ulonglong2*>(&As[kk * ASTR + ty * 8 + 4]);
                float4     bb  = *reinterpret_cast<const float4*>(&Bs[kk * BN + tx * 4]);
                u64 av[4] = {a01.x, a01.y, a23.x, a23.y};
                u64 bv[4] = {splat2(bb.x), splat2(bb.y), splat2(bb.z), splat2(bb.w)};
                #pragma unroll
                for (int p = 0; p < 4; p++)
                    #pragma unroll
                    for (int j = 0; j < 4; j++)
                        acc2[p][j] = fma2(av[p], bv[j], acc2[p][j]);
            }
            __syncthreads();
        }

        // --- epilogue for this U tile: bias + tanh + Vk-weighted fold into row logit
        int n0 = nt * BN + tx * 4;
        float4 vk = *reinterpret_cast<const float4*>(Vk + n0);       // Vk is [U,1]
        float4 uh = *reinterpret_cast<const float4*>(&g_uh[b * Uq + n0]);
        float uhv[4] = {uh.x, uh.y, uh.z, uh.w};
        float vkv[4] = {vk.x, vk.y, vk.z, vk.w};
        #pragma unroll
        for (int p = 0; p < 4; p++) {
            #pragma unroll
            for (int j = 0; j < 4; j++) {
                float lo, hi;
                unpack2(acc2[p][j], lo, hi);
                rowp[2 * p + 0] = fmaf(vkv[j], tanh_fast(lo + uhv[j]), rowp[2 * p + 0]);
                rowp[2 * p + 1] = fmaf(vkv[j], tanh_fast(hi + uhv[j]), rowp[2 * p + 1]);
            }
        }
    }

    // reduce partial logits across the 16 tx lanes per row
    if (tid < BM) red[tid] = 0.f;
    __syncthreads();
    #pragma unroll
    for (int i = 0; i < 8; i++) atomicAdd(&red[ty * 8 + i], rowp[i]);
    __syncthreads();
    if (tid < BM) g_logits[row0 + tid] = red[tid];
}

// ---------------------------------------------------------------------------
// Kernel 2: softmax over T per batch -> weights to d_out; also zeroes ctx
// (ctx must be zeroed before context_kernel's atomic accumulation; d_out is
//  poisoned to 0xAA by the harness.)
// ---------------------------------------------------------------------------
__global__ void softmax_kernel(float* __restrict__ out_w, float* __restrict__ ctx) {
    const int b = blockIdx.x;
    const int tid = threadIdx.x;   // 256
    __shared__ float sm[256];
    const float* lg = g_logits + b * Tq;

    // zero the context slice for this batch (512 floats, 2 per thread)
    ctx[b * Dq + tid] = 0.f;
    ctx[b * Dq + 256 + tid] = 0.f;

    float mx = -1e30f;
    for (int t = tid; t < Tq; t += 256) mx = fmaxf(mx, lg[t]);
    sm[tid] = mx; __syncthreads();
    for (int s = 128; s > 0; s >>= 1) {
        if (tid < s) sm[tid] = fmaxf(sm[tid], sm[tid + s]);
        __syncthreads();
    }
    mx = sm[0]; __syncthreads();

    float sum = 0.f;
    for (int t = tid; t < Tq; t += 256) sum += expf(lg[t] - mx);
    sm[tid] = sum; __syncthreads();
    for (int s = 128; s > 0; s >>= 1) {
        if (tid < s) sm[tid] += sm[tid + s];
        __syncthreads();
    }
    float inv = 1.f / sm[0];

    for (int t = tid; t < Tq; t += 256)
        out_w[b * Tq + t] = expf(lg[t] - mx) * inv;
}

// ---------------------------------------------------------------------------
// Kernel 3: context[b,d] = sum_t w[b,t] * features[b,t,d]
// grid (16 t-chunks, B), 256 threads. Each block: 128 t-rows, fully coalesced
// float4 row sweeps, 4-deep MLP; REDG (atomicAdd, no return) accumulation.
// ---------------------------------------------------------------------------
#define TCHUNK 128
__global__ __launch_bounds__(256, 8)
void context_kernel(const float* __restrict__ features,
                    const float* __restrict__ w,
                    float* __restrict__ ctx) {
    __shared__ float ws[TCHUNK];
    const int b  = blockIdx.y;
    const int t0 = blockIdx.x * TCHUNK;
    const int tid = threadIdx.x;
    const int d4 = tid & 127;         // which float4 of the 512-wide row
    const int tp = tid >> 7;          // 0/1: t-interleave

    if (tid < TCHUNK) ws[tid] = w[b * Tq + t0 + tid];
    __syncthreads();

    const float* fb = features + (long)b * Tq * Dq + (long)t0 * Dq + d4 * 4;
    float4 acc = make_float4(0.f, 0.f, 0.f, 0.f);
    #pragma unroll 4
    for (int i = tp; i < TCHUNK; i += 2) {
        float  wt = ws[i];
        float4 v  = *reinterpret_cast<const float4*>(fb + (long)i * Dq);
        acc.x = fmaf(wt, v.x, acc.x);
        acc.y = fmaf(wt, v.y, acc.y);
        acc.z = fmaf(wt, v.z, acc.z);
        acc.w = fmaf(wt, v.w, acc.w);
    }
    float* dst = ctx + b * Dq + d4 * 4;
    atomicAdd(dst + 0, acc.x);
    atomicAdd(dst + 1, acc.y);
    atomicAdd(dst + 2, acc.z);
    atomicAdd(dst + 3, acc.w);
}

// ---------------------------------------------------------------------------
extern "C" void kernel_launch(void* const* d_in, const int* in_sizes, int n_in,
                              void* d_out, int out_size) {
    const float* features = (const float*)d_in[0];  // [B,T,D]
    const float* hidden   = (const float*)d_in[1];  // [B,H]
    const float* Wk       = (const float*)d_in[2];  // [D,U]
    const float* Wb       = (const float*)d_in[3];  // [U]
    const float* Uk       = (const float*)d_in[4];  // [H,U]
    const float* Ub       = (const float*)d_in[5];  // [U]
    const float* Vk       = (const float*)d_in[6];  // [U,1]
    // d_in[7] = Vb [1]: uniform logit shift -> softmax-invariant -> unused.

    float* out  = (float*)d_out;
    float* ctx  = out;               // context_vector [B, D]  (tuple output 0)
    float* attw = out + Bq * Dq;     // attention_weights [B, T, 1] (tuple output 1)

    uh_kernel<<<dim3(Uq / 128, Bq), 128>>>(hidden, Uk, Ub, Wb);
    logits_kernel<<<(Bq * Tq) / BM, 256>>>(features, Wk, Vk);
    softmax_kernel<<<Bq, 256>>>(attw, ctx);
    context_kernel<<<dim3(Tq / TCHUNK, Bq), 256>>>(features, attw, ctx);
}

// round 4
// speedup vs baseline: 3.5669x; 2.7852x over previous
#include <cuda_runtime.h>
#include <cuda_fp16.h>
#include <math.h>

// Problem dims (fixed by the reference)
#define Bq 32
#define Tq 2048
#define Dq 512
#define Uq 512

// Scratch (no device allocation allowed -> __device__ globals)
__device__ float g_uh[Bq * Uq];        // hidden@Uk + Ub + Wb  (per b,u bias)
__device__ float g_logits[Bq * Tq];    // pre-softmax logits (Vb dropped: softmax-invariant)

// ---------------- small helpers ----------------
__device__ __forceinline__ float to_tf32(float x) {
    unsigned u;
    asm("cvt.rna.tf32.f32 %0, %1;" : "=r"(u) : "f"(x));
    return __uint_as_float(u);
}
__device__ __forceinline__ void mma_tf32(float4& d,
                                         unsigned a0, unsigned a1, unsigned a2, unsigned a3,
                                         unsigned b0, unsigned b1) {
    asm volatile(
        "mma.sync.aligned.m16n8k8.row.col.f32.tf32.tf32.f32 "
        "{%0,%1,%2,%3}, {%4,%5,%6,%7}, {%8,%9}, {%0,%1,%2,%3};"
        : "+f"(d.x), "+f"(d.y), "+f"(d.z), "+f"(d.w)
        : "r"(a0), "r"(a1), "r"(a2), "r"(a3), "r"(b0), "r"(b1));
}
__device__ __forceinline__ void cpasync16(unsigned dst_smem, const void* src) {
    asm volatile("cp.async.cg.shared.global [%0], [%1], 16;" :: "r"(dst_smem), "l"(src));
}
__device__ __forceinline__ unsigned h2tanh(unsigned x) {   // MUFU.TANH on 2 halves
    unsigned r;
    asm("tanh.approx.f16x2 %0, %1;" : "=r"(r) : "r"(x));
    return r;
}

// ---------------------------------------------------------------------------
// Kernel 0: g_uh[b,u] = sum_h hidden[b,h]*Uk[h,u] + Ub[u] + Wb[u]
// ---------------------------------------------------------------------------
__global__ void uh_kernel(const float* __restrict__ hidden,
                          const float* __restrict__ Uk,
                          const float* __restrict__ Ub,
                          const float* __restrict__ Wb) {
    int u = blockIdx.x * blockDim.x + threadIdx.x;   // [0,512)
    int b = blockIdx.y;                              // [0,32)
    float acc = Ub[u] + Wb[u];
    const float* h = hidden + b * 512;               // H = 512
    #pragma unroll 8
    for (int k = 0; k < 512; k++)
        acc = fmaf(h[k], Uk[k * Uq + u], acc);
    g_uh[b * Uq + u] = acc;
}

// ---------------------------------------------------------------------------
// Kernel 1 (hot): logits[b,t] = sum_u Vk[u]*tanh( (features@Wk)[b,t,u] + uh[b,u] )
// tf32 mma.sync m16n8k8. CTA: BM=64 rows x full U=512 (all accumulators in regs).
// 256 threads = 8 warps = 4 (M) x 2 (N). Per warp: m16 x n256 -> 32 mma tiles,
// acc = float4[8][4] = 128 regs. A (features tile) resident in SMEM, loaded ONCE.
// B (Wk) streamed in 16-k-row stages, double-buffered via cp.async.
// Epilogue in registers: +uh, tanh.approx.f16x2, Vk FFMA, shfl-reduce per row.
// ---------------------------------------------------------------------------
#define BM 64
#define KSTAGE 16
#define NSTAGE (Dq / KSTAGE)   // 32 stages
#define ASTR 516               // 516%32=4 -> a-frag LDS conflict-free
#define BSTR 520               // 520%32=8 -> b-frag LDS conflict-free

// smem (floats): A 64*516 =33024 | B 2*16*520 =16640 | uhs 512 | vks 512 | red 64
#define SMEM_FLOATS (BM * ASTR + 2 * KSTAGE * BSTR + Uq + Uq + BM)
#define SMEM_BYTES  (SMEM_FLOATS * 4)

__global__ __launch_bounds__(256, 1)
void logits_kernel(const float* __restrict__ features,
                   const float* __restrict__ Wk,
                   const float* __restrict__ Vk) {
    extern __shared__ float smem[];
    float* Asm = smem;                        // [64][516]
    float* Bsm = Asm + BM * ASTR;             // [2][16][520]
    float* uhs = Bsm + 2 * KSTAGE * BSTR;     // [512]
    float* vks = uhs + Uq;                    // [512]
    float* red = vks + Uq;                    // [64]

    const int tid  = threadIdx.x;
    const int lane = tid & 31;
    const int wid  = tid >> 5;
    const int wm   = wid >> 1;                // 0..3 (M warp)
    const int wn   = wid & 1;                 // 0..1 (N warp)
    const int g    = lane >> 2;               // 0..7
    const int t    = lane & 3;                // 0..3
    const long row0 = (long)blockIdx.x * BM;  // global (b,t) row
    const int b = (int)(row0 >> 11);          // 2048 rows per batch; CTA never straddles

    const unsigned bsm0 = (unsigned)__cvta_generic_to_shared(Bsm);

    // --- load A tile [64 x 512] once, tf32-rounded, coalesced ---
    #pragma unroll
    for (int i = 0; i < 32; i++) {
        int id = tid + i * 256;               // 0..8191 float4 slots
        int r  = id >> 7;                     // 0..63
        int k4 = id & 127;
        float4 v = *reinterpret_cast<const float4*>(features + (row0 + r) * Dq + k4 * 4);
        float* dst = Asm + r * ASTR + k4 * 4;
        dst[0] = to_tf32(v.x); dst[1] = to_tf32(v.y);
        dst[2] = to_tf32(v.z); dst[3] = to_tf32(v.w);
    }
    // --- uh row, Vk, red init ---
    for (int i = tid; i < Uq; i += 256) { uhs[i] = g_uh[b * Uq + i]; vks[i] = Vk[i]; }
    if (tid < BM) red[tid] = 0.f;

    // --- prefetch B stage 0 ---
    #pragma unroll
    for (int i = 0; i < 8; i++) {
        int id = tid + i * 256;               // 0..2047
        int r  = id >> 7;                     // 0..15
        int n4 = id & 127;
        cpasync16(bsm0 + (unsigned)((r * BSTR + n4 * 4) * 4), Wk + r * Uq + n4 * 4);
    }
    asm volatile("cp.async.commit_group;");

    float4 acc[8][4];
    #pragma unroll
    for (int nt = 0; nt < 8; nt++)
        #pragma unroll
        for (int j = 0; j < 4; j++) acc[nt][j] = make_float4(0.f, 0.f, 0.f, 0.f);

    #pragma unroll 1
    for (int s = 0; s < NSTAGE; s++) {
        const int buf = s & 1;
        // issue next stage copy
        if (s + 1 < NSTAGE) {
            const float* src = Wk + (s + 1) * KSTAGE * Uq;
            const unsigned dstb = bsm0 + (unsigned)(((1 - buf) * KSTAGE * BSTR) * 4);
            #pragma unroll
            for (int i = 0; i < 8; i++) {
                int id = tid + i * 256;
                int r  = id >> 7;
                int n4 = id & 127;
                cpasync16(dstb + (unsigned)((r * BSTR + n4 * 4) * 4), src + r * Uq + n4 * 4);
            }
            asm volatile("cp.async.commit_group;");
            asm volatile("cp.async.wait_group 1;");
        } else {
            asm volatile("cp.async.wait_group 0;");
        }
        __syncthreads();   // stage s visible to all; all done reading buf from s-2

        const float* Bst = Bsm + buf * KSTAGE * BSTR;
        #pragma unroll
        for (int k8 = 0; k8 < 2; k8++) {
            const int kb = s * KSTAGE + k8 * 8;
            const float* Ab = Asm + (wm * 16 + g) * ASTR + kb + t;
            unsigned a0 = __float_as_uint(Ab[0]);
            unsigned a1 = __float_as_uint(Ab[8 * ASTR]);
            unsigned a2 = __float_as_uint(Ab[4]);
            unsigned a3 = __float_as_uint(Ab[8 * ASTR + 4]);
            const float* Bb = Bst + (k8 * 8 + t) * BSTR + wn * 32 + g;
            #pragma unroll
            for (int nt = 0; nt < 8; nt++)
                #pragma unroll
                for (int j = 0; j < 4; j++) {
                    unsigned b0 = __float_as_uint(Bb[nt * 64 + j * 8]);
                    unsigned b1 = __float_as_uint(Bb[4 * BSTR + nt * 64 + j * 8]);
                    mma_tf32(acc[nt][j], a0, a1, a2, a3, b0, b1);
                }
        }
        __syncthreads();   // protect buf before stage s+2 overwrites it
    }

    // --- epilogue: x = d + uh; s = tanh(x) [f16x2]; rowsum += Vk*s ---
    float rs0 = 0.f, rs1 = 0.f;     // rows wm*16+g and +8
    #pragma unroll
    for (int nt = 0; nt < 8; nt++)
        #pragma unroll
        for (int j = 0; j < 4; j++) {
            const int cb = nt * 64 + wn * 32 + j * 8 + 2 * t;
            float uh0 = uhs[cb], uh1 = uhs[cb + 1];
            float vk0 = vks[cb], vk1 = vks[cb + 1];
            float4 d = acc[nt][j];
            // row g
            __half2 h0 = __floats2half2_rn(d.x + uh0, d.y + uh1);
            unsigned s0 = h2tanh(*reinterpret_cast<unsigned*>(&h0));
            float2 f0 = __half22float2(*reinterpret_cast<__half2*>(&s0));
            rs0 = fmaf(vk0, f0.x, rs0);
            rs0 = fmaf(vk1, f0.y, rs0);
            // row g+8
            __half2 h1 = __floats2half2_rn(d.z + uh0, d.w + uh1);
            unsigned s1 = h2tanh(*reinterpret_cast<unsigned*>(&h1));
            float2 f1 = __half22float2(*reinterpret_cast<__half2*>(&s1));
            rs1 = fmaf(vk0, f1.x, rs1);
            rs1 = fmaf(vk1, f1.y, rs1);
        }
    // reduce over the 4 lanes (t) sharing a row
    rs0 += __shfl_xor_sync(0xffffffffu, rs0, 1);
    rs0 += __shfl_xor_sync(0xffffffffu, rs0, 2);
    rs1 += __shfl_xor_sync(0xffffffffu, rs1, 1);
    rs1 += __shfl_xor_sync(0xffffffffu, rs1, 2);
    if (t == 0) {
        atomicAdd(&red[wm * 16 + g], rs0);       // 2 N-warps fold here
        atomicAdd(&red[wm * 16 + g + 8], rs1);
    }
    __syncthreads();
    if (tid < BM) g_logits[row0 + tid] = red[tid];
}

// ---------------------------------------------------------------------------
// Kernel 2: softmax over T per batch -> weights to d_out; also zeroes ctx
// ---------------------------------------------------------------------------
__global__ void softmax_kernel(float* __restrict__ out_w, float* __restrict__ ctx) {
    const int b = blockIdx.x;
    const int tid = threadIdx.x;   // 256
    __shared__ float sm[256];
    const float* lg = g_logits + b * Tq;

    ctx[b * Dq + tid] = 0.f;
    ctx[b * Dq + 256 + tid] = 0.f;

    float mx = -1e30f;
    for (int t = tid; t < Tq; t += 256) mx = fmaxf(mx, lg[t]);
    sm[tid] = mx; __syncthreads();
    for (int s = 128; s > 0; s >>= 1) {
        if (tid < s) sm[tid] = fmaxf(sm[tid], sm[tid + s]);
        __syncthreads();
    }
    mx = sm[0]; __syncthreads();

    float sum = 0.f;
    for (int t = tid; t < Tq; t += 256) sum += expf(lg[t] - mx);
    sm[tid] = sum; __syncthreads();
    for (int s = 128; s > 0; s >>= 1) {
        if (tid < s) sm[tid] += sm[tid + s];
        __syncthreads();
    }
    float inv = 1.f / sm[0];

    for (int t = tid; t < Tq; t += 256)
        out_w[b * Tq + t] = expf(lg[t] - mx) * inv;
}

// ---------------------------------------------------------------------------
// Kernel 3: context[b,d] = sum_t w[b,t] * features[b,t,d]   (28us, 62% HBM)
// ---------------------------------------------------------------------------
#define TCHUNK 128
__global__ __launch_bounds__(256, 8)
void context_kernel(const float* __restrict__ features,
                    const float* __restrict__ w,
                    float* __restrict__ ctx) {
    __shared__ float ws[TCHUNK];
    const int b  = blockIdx.y;
    const int t0 = blockIdx.x * TCHUNK;
    const int tid = threadIdx.x;
    const int d4 = tid & 127;
    const int tp = tid >> 7;

    if (tid < TCHUNK) ws[tid] = w[b * Tq + t0 + tid];
    __syncthreads();

    const float* fb = features + (long)b * Tq * Dq + (long)t0 * Dq + d4 * 4;
    float4 acc = make_float4(0.f, 0.f, 0.f, 0.f);
    #pragma unroll 4
    for (int i = tp; i < TCHUNK; i += 2) {
        float  wt = ws[i];
        float4 v  = *reinterpret_cast<const float4*>(fb + (long)i * Dq);
        acc.x = fmaf(wt, v.x, acc.x);
        acc.y = fmaf(wt, v.y, acc.y);
        acc.z = fmaf(wt, v.z, acc.z);
        acc.w = fmaf(wt, v.w, acc.w);
    }
    float* dst = ctx + b * Dq + d4 * 4;
    atomicAdd(dst + 0, acc.x);
    atomicAdd(dst + 1, acc.y);
    atomicAdd(dst + 2, acc.z);
    atomicAdd(dst + 3, acc.w);
}

// ---------------------------------------------------------------------------
extern "C" void kernel_launch(void* const* d_in, const int* in_sizes, int n_in,
                              void* d_out, int out_size) {
    const float* features = (const float*)d_in[0];  // [B,T,D]
    const float* hidden   = (const float*)d_in[1];  // [B,H]
    const float* Wk       = (const float*)d_in[2];  // [D,U]
    const float* Wb       = (const float*)d_in[3];  // [U]
    const float* Uk       = (const float*)d_in[4];  // [H,U]
    const float* Ub       = (const float*)d_in[5];  // [U]
    const float* Vk       = (const float*)d_in[6];  // [U,1]
    // d_in[7] = Vb [1]: uniform logit shift -> softmax-invariant -> unused.

    float* out  = (float*)d_out;
    float* ctx  = out;               // context_vector [B, D]  (tuple output 0)
    float* attw = out + Bq * Dq;     // attention_weights [B, T, 1] (tuple output 1)

    cudaFuncSetAttribute(logits_kernel,
                         cudaFuncAttributeMaxDynamicSharedMemorySize, SMEM_BYTES);

    uh_kernel<<<dim3(Uq / 128, Bq), 128>>>(hidden, Uk, Ub, Wb);
    logits_kernel<<<(Bq * Tq) / BM, 256, SMEM_BYTES>>>(features, Wk, Vk);
    softmax_kernel<<<Bq, 256>>>(attw, ctx);
    context_kernel<<<dim3(Tq / TCHUNK, Bq), 256>>>(features, attw, ctx);
}

// round 7
// speedup vs baseline: 4.4621x; 1.2510x over previous
#include <cuda_runtime.h>
#include <cuda_fp16.h>
#include <math.h>

// Problem dims (fixed by the reference)
#define Bq 32
#define Tq 2048
#define Dq 512
#define Uq 512

// Scratch (no device allocation allowed -> __device__ globals)
__device__ float  g_uh[Bq * Uq];      // hidden@Uk + Ub + Wb  (per b,u bias)
__device__ float  g_logits[Bq * Tq];  // pre-softmax logits (Vb dropped: softmax-invariant)
__device__ __half g_wkh[Uq * Dq];     // Wk^T as half, [u][d] (B operand, K-contiguous)

// ---------------- helpers ----------------
__device__ __forceinline__ unsigned smem_u32(const void* p) {
    unsigned a;
    asm("{ .reg .u64 t; cvta.to.shared.u64 t, %1; cvt.u32.u64 %0, t; }" : "=r"(a) : "l"(p));
    return a;
}
__device__ __forceinline__ void cpasync16(unsigned dst, const void* src) {
    asm volatile("cp.async.cg.shared.global [%0], [%1], 16;" :: "r"(dst), "l"(src));
}
__device__ __forceinline__ unsigned h2tanh(unsigned x) {   // MUFU.TANH on 2 halves
    unsigned r;
    asm("tanh.approx.f16x2 %0, %1;" : "=r"(r) : "r"(x));
    return r;
}
__device__ __forceinline__ void ldmx4(unsigned* r, unsigned addr) {
    asm volatile("ldmatrix.sync.aligned.m8n8.x4.shared.b16 {%0,%1,%2,%3}, [%4];"
                 : "=r"(r[0]), "=r"(r[1]), "=r"(r[2]), "=r"(r[3]) : "r"(addr));
}
__device__ __forceinline__ void mma_f16(float4& d, const unsigned* a,
                                        unsigned b0, unsigned b1) {
    asm volatile(
        "mma.sync.aligned.m16n8k16.row.col.f32.f16.f16.f32 "
        "{%0,%1,%2,%3}, {%4,%5,%6,%7}, {%8,%9}, {%0,%1,%2,%3};"
        : "+f"(d.x), "+f"(d.y), "+f"(d.z), "+f"(d.w)
        : "r"(a[0]), "r"(a[1]), "r"(a[2]), "r"(a[3]), "r"(b0), "r"(b1));
}

// ---------------------------------------------------------------------------
// Kernel 0a: g_uh[b,u] = hidden@Uk + Ub + Wb
// ---------------------------------------------------------------------------
__global__ void uh_kernel(const float* __restrict__ hidden,
                          const float* __restrict__ Uk,
                          const float* __restrict__ Ub,
                          const float* __restrict__ Wb) {
    int u = blockIdx.x * blockDim.x + threadIdx.x;
    int b = blockIdx.y;
    float acc = Ub[u] + Wb[u];
    const float* h = hidden + b * 512;
    #pragma unroll 8
    for (int k = 0; k < 512; k++)
        acc = fmaf(h[k], Uk[k * Uq + u], acc);
    g_uh[b * Uq + u] = acc;
}

// ---------------------------------------------------------------------------
// Kernel 0b: g_wkh[u][d] = half(Wk[d][u])
// ---------------------------------------------------------------------------
__global__ void wkh_kernel(const float* __restrict__ Wk) {
    __shared__ float t[32][33];
    int bu = blockIdx.x * 32, bd = blockIdx.y * 32;
    int tx = threadIdx.x, ty = threadIdx.y;       // 32 x 8
    #pragma unroll
    for (int i = 0; i < 32; i += 8)
        t[ty + i][tx] = Wk[(bd + ty + i) * Uq + bu + tx];   // t[d][u]
    __syncthreads();
    #pragma unroll
    for (int i = 0; i < 32; i += 8)
        g_wkh[(bu + ty + i) * Dq + bd + tx] = __float2half(t[tx][ty + i]);
}

// ---------------------------------------------------------------------------
// Kernel 1 (hot): logits via fp16 mma.sync m16n8k16 + ldmatrix.
// CTA: BM=64 rows x N=512. 8 warps; warp w covers m64 x n64 (n0 = w*64).
// acc float4[4][8] = 128 regs. K staged 32-wide, double-buffered:
//   A: f32 global -> regs -> half smem (80B-padded rows, conflict-free ldmatrix)
//   B: cp.async from pre-converted g_wkh.
// Epilogue: +uh, tanh.approx.f16x2, Vk FMA, shfl + smem reduce.
// ---------------------------------------------------------------------------
#define BM 64
#define KS 32
#define NSTG (Dq / KS)          // 16 stages, 2 k16-steps each
#define ROWB 80                 // padded row pitch in bytes (40 halves)
#define ABUF 5120               // one A buffer: 64 rows * 80 B
#define BBUF 40960              // one B buffer: 512 rows * 80 B

#define SM_A    0                       // 2 x ABUF = 10240
#define SM_B    10240                   // 2 x BBUF = 81920
#define SM_UH   (SM_B + 2 * BBUF)       // 92160
#define SM_VK   (SM_UH + 2048)          // 94208
#define SM_RED  (SM_VK + 2048)          // 96256
#define SM_TOT  (SM_RED + 256)          // 96512 bytes

__global__ __launch_bounds__(256, 1)
void logits_kernel(const float* __restrict__ features,
                   const float* __restrict__ Vk) {
    extern __shared__ char smem[];
    const unsigned sb = smem_u32(smem);
    const int tid = threadIdx.x, lane = tid & 31, wid = tid >> 5;
    const int n0w = wid * 64;                   // warp's N offset
    const long row0 = (long)blockIdx.x * BM;
    const int b = (int)(row0 >> 11);

    float* uhs = (float*)(smem + SM_UH);
    float* vks = (float*)(smem + SM_VK);
    float* red = (float*)(smem + SM_RED);

    for (int i = tid; i < Uq; i += 256) { uhs[i] = g_uh[b * Uq + i]; vks[i] = Vk[i]; }
    if (tid < BM) red[tid] = 0.f;

    // per-thread fill indices
    const int ar_r  = tid >> 2;                 // A row 0..63
    const int ar_k4a = (tid & 3) * 2;           // two consecutive float4 slots
    const int lr = lane & 7, sect = lane >> 3;  // ldmatrix lane addressing

    float4 acc[4][8];
    #pragma unroll
    for (int mi = 0; mi < 4; mi++)
        #pragma unroll
        for (int nt = 0; nt < 8; nt++) acc[mi][nt] = make_float4(0.f, 0.f, 0.f, 0.f);

    float4 ar[2][2];    // double-buffered A fragments in regs

    auto loadA = [&](int s, int pb) {
        #pragma unroll
        for (int i = 0; i < 2; i++)
            ar[pb][i] = *reinterpret_cast<const float4*>(
                features + (row0 + ar_r) * Dq + s * KS + (ar_k4a + i) * 4);
    };
    auto storeA = [&](int buf, int pb) {
        #pragma unroll
        for (int i = 0; i < 2; i++) {
            float4 v = ar[pb][i];
            __half2 h0 = __floats2half2_rn(v.x, v.y);
            __half2 h1 = __floats2half2_rn(v.z, v.w);
            uint2 u = make_uint2(*reinterpret_cast<unsigned*>(&h0),
                                 *reinterpret_cast<unsigned*>(&h1));
            *reinterpret_cast<uint2*>(smem + SM_A + buf * ABUF +
                                      ar_r * ROWB + (ar_k4a + i) * 8) = u;
        }
    };
    auto fillB = [&](int s, int buf) {
        const unsigned bb = sb + SM_B + buf * BBUF;
        #pragma unroll
        for (int i = 0; i < 8; i++) {
            int idx = tid + i * 256;            // 0..2047
            int n = idx >> 2, c = idx & 3;
            cpasync16(bb + (unsigned)(n * ROWB + c * 16),
                      g_wkh + n * Dq + s * KS + c * 8);
        }
    };

    loadA(0, 0);
    fillB(0, 0);
    asm volatile("cp.async.commit_group;");

    for (int s = 0; s < NSTG; s++) {
        const int buf = s & 1;
        if (s + 1 < NSTG) {
            fillB(s + 1, 1 - buf);
            asm volatile("cp.async.commit_group;");
            loadA(s + 1, 1 - buf);
        }
        storeA(buf, buf);
        if (s + 1 < NSTG) asm volatile("cp.async.wait_group 1;");
        else              asm volatile("cp.async.wait_group 0;");
        __syncthreads();

        const unsigned ab = sb + SM_A + buf * ABUF;
        const unsigned bb = sb + SM_B + buf * BBUF;
        #pragma unroll
        for (int k16 = 0; k16 < 2; k16++) {
            const int kb = k16 * 16;            // halves offset within stage row
            unsigned af[4][4], bf[4][4];
            // A frags: mat order (m0:8,k0:8),(m8:16,k0:8),(m0:8,k8:16),(m8:16,k8:16)
            #pragma unroll
            for (int mi = 0; mi < 4; mi++)
                ldmx4(af[mi], ab + (unsigned)((mi * 16 + (sect & 1) * 8 + lr) * ROWB
                                              + (kb + (sect >> 1) * 8) * 2));
            // B frags: mat order (n0:8,k0:8),(n0:8,k8:16),(n8:16,k0:8),(n8:16,k8:16)
            #pragma unroll
            for (int nj = 0; nj < 4; nj++)
                ldmx4(bf[nj], bb + (unsigned)((n0w + nj * 16 + (sect >> 1) * 8 + lr) * ROWB
                                              + (kb + (sect & 1) * 8) * 2));
            #pragma unroll
            for (int mi = 0; mi < 4; mi++)
                #pragma unroll
                for (int nj = 0; nj < 4; nj++) {
                    mma_f16(acc[mi][2 * nj],     af[mi], bf[nj][0], bf[nj][1]);
                    mma_f16(acc[mi][2 * nj + 1], af[mi], bf[nj][2], bf[nj][3]);
                }
        }
        __syncthreads();
    }

    // ---- epilogue: x = d + uh; tanh (f16x2); rowsum += Vk * tanh ----
    const int g = lane >> 2, t = lane & 3;
    float rs[8];
    #pragma unroll
    for (int i = 0; i < 8; i++) rs[i] = 0.f;
    #pragma unroll
    for (int mi = 0; mi < 4; mi++)
        #pragma unroll
        for (int nt = 0; nt < 8; nt++) {
            const int n = n0w + nt * 8 + 2 * t;
            float uh0 = uhs[n], uh1 = uhs[n + 1];
            float vk0 = vks[n], vk1 = vks[n + 1];
            float4 d = acc[mi][nt];
            __half2 h0 = __floats2half2_rn(d.x + uh0, d.y + uh1);
            unsigned t0 = h2tanh(*reinterpret_cast<unsigned*>(&h0));
            float2 f0 = __half22float2(*reinterpret_cast<__half2*>(&t0));
            rs[mi * 2]     = fmaf(vk0, f0.x, fmaf(vk1, f0.y, rs[mi * 2]));
            __half2 h1 = __floats2half2_rn(d.z + uh0, d.w + uh1);
            unsigned t1 = h2tanh(*reinterpret_cast<unsigned*>(&h1));
            float2 f1 = __half22float2(*reinterpret_cast<__half2*>(&t1));
            rs[mi * 2 + 1] = fmaf(vk0, f1.x, fmaf(vk1, f1.y, rs[mi * 2 + 1]));
        }
    #pragma unroll
    for (int i = 0; i < 8; i++) {
        rs[i] += __shfl_xor_sync(0xffffffffu, rs[i], 1);
        rs[i] += __shfl_xor_sync(0xffffffffu, rs[i], 2);
    }
    if (t == 0) {
        #pragma unroll
        for (int mi = 0; mi < 4; mi++) {
            atomicAdd(&red[mi * 16 + g],     rs[mi * 2]);
            atomicAdd(&red[mi * 16 + 8 + g], rs[mi * 2 + 1]);
        }
    }
    __syncthreads();
    if (tid < BM) g_logits[row0 + tid] = red[tid];
}

// ---------------------------------------------------------------------------
// Kernel 2: softmax over T per batch -> weights to d_out; also zeroes ctx
// ---------------------------------------------------------------------------
__global__ void softmax_kernel(float* __restrict__ out_w, float* __restrict__ ctx) {
    const int b = blockIdx.x;
    const int tid = threadIdx.x;   // 256
    __shared__ float sm[256];
    const float* lg = g_logits + b * Tq;

    ctx[b * Dq + tid] = 0.f;
    ctx[b * Dq + 256 + tid] = 0.f;

    float mx = -1e30f;
    for (int t = tid; t < Tq; t += 256) mx = fmaxf(mx, lg[t]);
    sm[tid] = mx; __syncthreads();
    for (int s = 128; s > 0; s >>= 1) {
        if (tid < s) sm[tid] = fmaxf(sm[tid], sm[tid + s]);
        __syncthreads();
    }
    mx = sm[0]; __syncthreads();

    float sum = 0.f;
    for (int t = tid; t < Tq; t += 256) sum += expf(lg[t] - mx);
    sm[tid] = sum; __syncthreads();
    for (int s = 128; s > 0; s >>= 1) {
        if (tid < s) sm[tid] += sm[tid + s];
        __syncthreads();
    }
    float inv = 1.f / sm[0];

    for (int t = tid; t < Tq; t += 256)
        out_w[b * Tq + t] = expf(lg[t] - mx) * inv;
}

// ---------------------------------------------------------------------------
// Kernel 3: context[b,d] = sum_t w[b,t] * features[b,t,d]
// ---------------------------------------------------------------------------
#define TCHUNK 128
__global__ __launch_bounds__(256, 8)
void context_kernel(const float* __restrict__ features,
                    const float* __restrict__ w,
                    float* __restrict__ ctx) {
    __shared__ float ws[TCHUNK];
    const int b  = blockIdx.y;
    const int t0 = blockIdx.x * TCHUNK;
    const int tid = threadIdx.x;
    const int d4 = tid & 127;
    const int tp = tid >> 7;

    if (tid < TCHUNK) ws[tid] = w[b * Tq + t0 + tid];
    __syncthreads();

    const float* fb = features + (long)b * Tq * Dq + (long)t0 * Dq + d4 * 4;
    float4 acc = make_float4(0.f, 0.f, 0.f, 0.f);
    #pragma unroll 4
    for (int i = tp; i < TCHUNK; i += 2) {
        float  wt = ws[i];
        float4 v  = *reinterpret_cast<const float4*>(fb + (long)i * Dq);
        acc.x = fmaf(wt, v.x, acc.x);
        acc.y = fmaf(wt, v.y, acc.y);
        acc.z = fmaf(wt, v.z, acc.z);
        acc.w = fmaf(wt, v.w, acc.w);
    }
    float* dst = ctx + b * Dq + d4 * 4;
    atomicAdd(dst + 0, acc.x);
    atomicAdd(dst + 1, acc.y);
    atomicAdd(dst + 2, acc.z);
    atomicAdd(dst + 3, acc.w);
}

// ---------------------------------------------------------------------------
extern "C" void kernel_launch(void* const* d_in, const int* in_sizes, int n_in,
                              void* d_out, int out_size) {
    const float* features = (const float*)d_in[0];  // [B,T,D]
    const float* hidden   = (const float*)d_in[1];  // [B,H]
    const float* Wk       = (const float*)d_in[2];  // [D,U]
    const float* Wb       = (const float*)d_in[3];  // [U]
    const float* Uk       = (const float*)d_in[4];  // [H,U]
    const float* Ub       = (const float*)d_in[5];  // [U]
    const float* Vk       = (const float*)d_in[6];  // [U,1]
    // d_in[7] = Vb [1]: uniform logit shift -> softmax-invariant -> unused.

    float* out  = (float*)d_out;
    float* ctx  = out;               // context_vector [B, D]  (tuple output 0)
    float* attw = out + Bq * Dq;     // attention_weights [B, T, 1] (tuple output 1)

    cudaFuncSetAttribute(logits_kernel,
                         cudaFuncAttributeMaxDynamicSharedMemorySize, SM_TOT);

    uh_kernel<<<dim3(Uq / 128, Bq), 128>>>(hidden, Uk, Ub, Wb);
    wkh_kernel<<<dim3(16, 16), dim3(32, 8)>>>(Wk);
    logits_kernel<<<(Bq * Tq) / BM, 256, SM_TOT>>>(features, Vk);
    softmax_kernel<<<Bq, 256>>>(attw, ctx);
    context_kernel<<<dim3(Tq / TCHUNK, Bq), 256>>>(features, attw, ctx);
}